// round 1
// baseline (speedup 1.0000x reference)
#include <cuda_runtime.h>
#include <cuda_bf16.h>
#include <math.h>

#define EPS 1e-8f

// C=1024, S=16, D=512
#define C_CLUST 1024
#define S_SAMP  16
#define D_DIM   512
#define NROWS   (C_CLUST * S_SAMP)   // 16384

// Scratch (static device globals; no allocation at runtime)
__device__ float g_meant[D_DIM * C_CLUST];   // mean centroids TRANSPOSED: [d][k]
__device__ float g_nmean[C_CLUST];           // ||mean_c[k]||
__device__ float g_nx[NROWS];                // ||x[j,i]||
__device__ float g_sp[NROWS];                // sim_pos[j,i]
__device__ float g_partial[C_CLUST];         // per-cluster partial loss sums

// ---------------------------------------------------------------------------
// Kernel 1: per-cluster stats. One block per cluster j.
//  - mean_c[j] (stored transposed), ||mean||, per-sample ||x||, sim_pos
// ---------------------------------------------------------------------------
__global__ void __launch_bounds__(256) k1_stats(const float* __restrict__ x)
{
    __shared__ float xs[S_SAMP * D_DIM];   // 32 KB
    __shared__ float ssum[D_DIM];          // raw column sums
    __shared__ float sred[8];
    __shared__ float s_sumsq;

    const int j   = blockIdx.x;
    const int tid = threadIdx.x;

    // Load x[j] slab (16x512 fp32) via float4
    const float4* gx = (const float4*)(x + (size_t)j * S_SAMP * D_DIM);
    float4* xs4 = (float4*)xs;
    #pragma unroll
    for (int it = 0; it < 8; it++) xs4[tid + it * 256] = gx[tid + it * 256];
    __syncthreads();

    // Column sums over S for 2 d's per thread; write transposed mean to global
    const int d0 = tid, d1 = tid + 256;
    float s0 = 0.f, s1 = 0.f;
    #pragma unroll
    for (int i = 0; i < S_SAMP; i++) {
        s0 += xs[i * D_DIM + d0];
        s1 += xs[i * D_DIM + d1];
    }
    ssum[d0] = s0;
    ssum[d1] = s1;
    g_meant[d0 * C_CLUST + j] = s0 * (1.f / 16.f);
    g_meant[d1 * C_CLUST + j] = s1 * (1.f / 16.f);

    // ||sum||^2 block reduction
    float p = s0 * s0 + s1 * s1;
    #pragma unroll
    for (int off = 16; off; off >>= 1) p += __shfl_down_sync(0xffffffffu, p, off);
    if ((tid & 31) == 0) sred[tid >> 5] = p;
    __syncthreads();
    if (tid == 0) {
        float t = 0.f;
        #pragma unroll
        for (int wi = 0; wi < 8; wi++) t += sred[wi];
        s_sumsq = t;
        g_nmean[j] = sqrtf(t) * (1.f / 16.f);
    }
    __syncthreads();
    const float sumsq = s_sumsq;

    // Per-row: ||x||^2 and dot(x, sum). Warp w handles rows w and w+8.
    const int w = tid >> 5, l = tid & 31;
    #pragma unroll
    for (int rr = 0; rr < 2; rr++) {
        const int i = w + rr * 8;
        float nx2 = 0.f, dt = 0.f;
        #pragma unroll
        for (int c = 0; c < 16; c++) {
            const int d = l + c * 32;
            const float a = xs[i * D_DIM + d];
            nx2 += a * a;
            dt  += a * ssum[d];
        }
        #pragma unroll
        for (int off = 16; off; off >>= 1) {
            nx2 += __shfl_down_sync(0xffffffffu, nx2, off);
            dt  += __shfl_down_sync(0xffffffffu, dt,  off);
        }
        if (l == 0) {
            const float loo_dot = (dt - nx2) * (1.f / 15.f);
            const float nloo2   = fmaxf((sumsq - 2.f * dt + nx2) * (1.f / 225.f), 0.f);
            const float nx      = sqrtf(nx2);
            const float sp      = loo_dot / fmaxf(nx * sqrtf(nloo2), EPS);
            g_nx[j * S_SAMP + i] = nx;
            g_sp[j * S_SAMP + i] = sp;
        }
    }
}

// ---------------------------------------------------------------------------
// Kernel 2: fused GEMM + logsumexp. One block per cluster j (16 rows).
// 256 threads: ty = tid>>6 owns rows {4ty..4ty+3}; tx = tid&63 owns 4 ks of
// each 256-wide k-tile. 4x4 register micro-tile over d-chunks of 8.
// ---------------------------------------------------------------------------
#define KT 256
#define DC 8

__global__ void __launch_bounds__(256) k2_gemm_lse(const float* __restrict__ x,
                                                   const float* __restrict__ wptr)
{
    __shared__ float xs[S_SAMP * D_DIM];   // 32 KB x slab
    __shared__ float mt[DC * KT];          // 8 KB mean tile, layout [dd][kk]
    __shared__ float red[S_SAMP * 64];     // 4 KB esum reduction
    __shared__ float s_nx[S_SAMP], s_sp[S_SAMP];
    __shared__ float rowloss[S_SAMP];

    const int j   = blockIdx.x;
    const int tid = threadIdx.x;
    const int ty  = tid >> 6;   // 0..3
    const int tx  = tid & 63;   // 0..63

    // Load x slab + per-row stats
    const float4* gx = (const float4*)(x + (size_t)j * S_SAMP * D_DIM);
    float4* xs4 = (float4*)xs;
    #pragma unroll
    for (int it = 0; it < 8; it++) xs4[tid + it * 256] = gx[tid + it * 256];
    if (tid < S_SAMP) {
        s_nx[tid] = g_nx[j * S_SAMP + tid];
        s_sp[tid] = g_sp[j * S_SAMP + tid];
    }
    __syncthreads();

    const float wp = log1pf(__expf(wptr[0]));   // softplus(w)

    float esum[4] = {0.f, 0.f, 0.f, 0.f};

    for (int kb = 0; kb < C_CLUST; kb += KT) {
        float acc[4][4] = {};

        for (int dblk = 0; dblk < D_DIM; dblk += DC) {
            __syncthreads();   // previous-chunk readers done before overwrite
            // Load mean tile: DC rows x KT ks = 512 float4, 2 per thread,
            // perfectly coalesced from transposed global layout.
            #pragma unroll
            for (int it = 0; it < 2; it++) {
                const int idx = tid + it * 256;  // 0..511
                const int dd  = idx >> 6;
                const int kk  = idx & 63;
                ((float4*)mt)[idx] =
                    ((const float4*)(g_meant + (size_t)(dblk + dd) * C_CLUST + kb))[kk];
            }
            __syncthreads();

            #pragma unroll
            for (int ds = 0; ds < DC; ds += 4) {
                float4 xf[4];
                #pragma unroll
                for (int r = 0; r < 4; r++)
                    xf[r] = *(const float4*)(xs + (ty * 4 + r) * D_DIM + dblk + ds);
                #pragma unroll
                for (int dd = 0; dd < 4; dd++) {
                    const float4 mv = *(const float4*)(mt + (ds + dd) * KT + tx * 4);
                    #pragma unroll
                    for (int r = 0; r < 4; r++) {
                        const float xv = ((const float*)&xf[r])[dd];
                        acc[r][0] += xv * mv.x;
                        acc[r][1] += xv * mv.y;
                        acc[r][2] += xv * mv.z;
                        acc[r][3] += xv * mv.w;
                    }
                }
            }
        }

        // Epilogue for this k-tile: normalize, diagonal swap, exp-accumulate
        const float4 nm = *(const float4*)(g_nmean + kb + tx * 4);
        const float nmv[4] = {nm.x, nm.y, nm.z, nm.w};
        #pragma unroll
        for (int r = 0; r < 4; r++) {
            const int row = ty * 4 + r;
            const float nx = s_nx[row];
            const float sp = s_sp[row];
            #pragma unroll
            for (int kk = 0; kk < 4; kk++) {
                const int k = kb + tx * 4 + kk;
                float sim = acc[r][kk] / fmaxf(nx * nmv[kk], EPS);
                if (k == j) sim = sp;
                esum[r] += __expf(wp * sim);
            }
        }
    }

    // Reduce esum across the 64 tx threads per row
    #pragma unroll
    for (int r = 0; r < 4; r++) red[(ty * 4 + r) * 64 + tx] = esum[r];
    __syncthreads();

    const int w = tid >> 5, l = tid & 31;
    #pragma unroll
    for (int rr = 0; rr < 2; rr++) {
        const int row = w * 2 + rr;
        float v = red[row * 64 + l] + red[row * 64 + l + 32];
        #pragma unroll
        for (int off = 16; off; off >>= 1) v += __shfl_down_sync(0xffffffffu, v, off);
        if (l == 0) rowloss[row] = logf(v) - wp * s_sp[row];
    }
    __syncthreads();

    if (tid == 0) {
        float t = 0.f;
        #pragma unroll
        for (int r = 0; r < S_SAMP; r++) t += rowloss[r];
        g_partial[j] = t;
    }
}

// ---------------------------------------------------------------------------
// Kernel 3: final reduce over 1024 cluster partials
// ---------------------------------------------------------------------------
__global__ void __launch_bounds__(256) k3_reduce(float* __restrict__ out)
{
    __shared__ float sred[8];
    const int tid = threadIdx.x;
    float p = 0.f;
    #pragma unroll
    for (int i = tid; i < C_CLUST; i += 256) p += g_partial[i];
    #pragma unroll
    for (int off = 16; off; off >>= 1) p += __shfl_down_sync(0xffffffffu, p, off);
    if ((tid & 31) == 0) sred[tid >> 5] = p;
    __syncthreads();
    if (tid == 0) {
        float t = 0.f;
        #pragma unroll
        for (int wi = 0; wi < 8; wi++) t += sred[wi];
        out[0] = t * (1.f / (float)NROWS);
    }
}

extern "C" void kernel_launch(void* const* d_in, const int* in_sizes, int n_in,
                              void* d_out, int out_size)
{
    const float* x = (const float*)d_in[0];
    const float* w = (const float*)d_in[1];
    // b cancels in the loss: lse(wp*sim + b) - (wp*sim_pos + b) is b-independent.
    float* out = (float*)d_out;

    k1_stats<<<C_CLUST, 256>>>(x);
    k2_gemm_lse<<<C_CLUST, 256>>>(x, w);
    k3_reduce<<<1, 256>>>(out);
}

// round 4
// speedup vs baseline: 7.6463x; 7.6463x over previous
#include <cuda_runtime.h>
#include <cuda_bf16.h>
#include <math.h>
#include <stdint.h>

#define EPS 1e-8f

#define C_CLUST 1024
#define S_SAMP  16
#define D_DIM   512
#define NROWS   (C_CLUST * S_SAMP)   // 16384

// ---- k2 tiling ----
#define BM 128                  // rows per CTA
#define NT 256                  // N-tile (centroids per tile) -> 4 tiles
#define KC 64                   // K-chunk (bf16, 128B rows)
#define NCHUNK 32               // 4 nt * 8 kc
#define A_BYTES   (BM * D_DIM * 2)        // 128 KB (all 8 K-chunks resident)
#define B_CHUNK_B (NT * KC * 2)           // 32 KB
#define DYN_SMEM  (A_BYTES + 2 * B_CHUNK_B + 1024)

// ---------------------------------------------------------------------------
// Scratch (static device globals)
// ---------------------------------------------------------------------------
__device__ __nv_bfloat16 g_Abf[NROWS * D_DIM];    // 16 MB
__device__ __nv_bfloat16 g_Bbf[C_CLUST * D_DIM];  // 1 MB (mean centroids [k][d])
__device__ float g_invnm[C_CLUST];
__device__ float g_invnx[NROWS];
__device__ float g_sp[NROWS];                     // sim_pos (exact fp32)
__device__ float g_partial[C_CLUST];

// ---------------------------------------------------------------------------
// helpers
// ---------------------------------------------------------------------------
__device__ __forceinline__ uint32_t smem_u32(const void* p) {
    uint32_t a;
    asm("{ .reg .u64 t; cvta.to.shared.u64 t, %1; cvt.u32.u64 %0, t; }" : "=r"(a) : "l"(p));
    return a;
}
__device__ __forceinline__ void cp_async16(uint32_t dst, const void* src) {
    asm volatile("cp.async.cg.shared.global [%0], [%1], 16;\n" :: "r"(dst), "l"(src) : "memory");
}
__device__ __forceinline__ void cp_commit() {
    asm volatile("cp.async.commit_group;\n" ::: "memory");
}
template <int N> __device__ __forceinline__ void cp_wait() {
    asm volatile("cp.async.wait_group %0;\n" :: "n"(N) : "memory");
}
__device__ __forceinline__ void ldsm4(uint32_t* r, uint32_t addr) {
    asm volatile("ldmatrix.sync.aligned.m8n8.x4.shared.b16 {%0,%1,%2,%3}, [%4];"
                 : "=r"(r[0]), "=r"(r[1]), "=r"(r[2]), "=r"(r[3]) : "r"(addr));
}
__device__ __forceinline__ void mma16816(float* c, const uint32_t* a, uint32_t b0, uint32_t b1) {
    asm volatile("mma.sync.aligned.m16n8k16.row.col.f32.bf16.bf16.f32 "
                 "{%0,%1,%2,%3}, {%4,%5,%6,%7}, {%8,%9}, {%0,%1,%2,%3};"
                 : "+f"(c[0]), "+f"(c[1]), "+f"(c[2]), "+f"(c[3])
                 : "r"(a[0]), "r"(a[1]), "r"(a[2]), "r"(a[3]), "r"(b0), "r"(b1));
}
// swizzled address inside a [rows][64 bf16] tile (128B rows): 16B segment xor
__device__ __forceinline__ uint32_t sw_addr(uint32_t base, int row, int kseg) {
    return base + (uint32_t)(row << 7) + (uint32_t)(((kseg ^ (row & 7)) & 7) << 4);
}

// ---------------------------------------------------------------------------
// Kernel 1: per-cluster stats + bf16 conversion (A rows, B centroids).
// ---------------------------------------------------------------------------
__global__ void __launch_bounds__(256) k1_stats(const float* __restrict__ x)
{
    __shared__ float xs[S_SAMP * D_DIM];   // 32 KB
    __shared__ float ssum[D_DIM];
    __shared__ float sred[8];
    __shared__ float s_sumsq;

    const int j   = blockIdx.x;
    const int tid = threadIdx.x;

    const float4* gx = (const float4*)(x + (size_t)j * S_SAMP * D_DIM);
    float4* xs4 = (float4*)xs;
    #pragma unroll
    for (int it = 0; it < 8; it++) xs4[tid + it * 256] = gx[tid + it * 256];
    __syncthreads();

    // bf16 A conversion
    #pragma unroll
    for (int it = 0; it < 8; it++) {
        const int i4 = tid + it * 256;             // 0..2047
        const float4 v = xs4[i4];
        unsigned short h0 = __bfloat16_as_ushort(__float2bfloat16(v.x));
        unsigned short h1 = __bfloat16_as_ushort(__float2bfloat16(v.y));
        unsigned short h2 = __bfloat16_as_ushort(__float2bfloat16(v.z));
        unsigned short h3 = __bfloat16_as_ushort(__float2bfloat16(v.w));
        ((uint2*)g_Abf)[(size_t)j * 2048 + i4] =
            make_uint2(((uint32_t)h1 << 16) | h0, ((uint32_t)h3 << 16) | h2);
    }

    // column sums over S
    const int d0 = tid, d1 = tid + 256;
    float s0 = 0.f, s1 = 0.f;
    #pragma unroll
    for (int i = 0; i < S_SAMP; i++) {
        s0 += xs[i * D_DIM + d0];
        s1 += xs[i * D_DIM + d1];
    }
    ssum[d0] = s0;
    ssum[d1] = s1;
    g_Bbf[(size_t)j * D_DIM + d0] = __float2bfloat16(s0 * (1.f / 16.f));
    g_Bbf[(size_t)j * D_DIM + d1] = __float2bfloat16(s1 * (1.f / 16.f));

    float p = s0 * s0 + s1 * s1;
    #pragma unroll
    for (int off = 16; off; off >>= 1) p += __shfl_down_sync(0xffffffffu, p, off);
    if ((tid & 31) == 0) sred[tid >> 5] = p;
    __syncthreads();
    if (tid == 0) {
        float t = 0.f;
        #pragma unroll
        for (int wi = 0; wi < 8; wi++) t += sred[wi];
        s_sumsq = t;
        g_invnm[j] = 16.f / sqrtf(t);
    }
    __syncthreads();
    const float sumsq = s_sumsq;

    const int w = tid >> 5, l = tid & 31;
    #pragma unroll
    for (int rr = 0; rr < 2; rr++) {
        const int i = w + rr * 8;
        float nx2 = 0.f, dt = 0.f;
        #pragma unroll
        for (int c = 0; c < 16; c++) {
            const int d = l + c * 32;
            const float a = xs[i * D_DIM + d];
            nx2 += a * a;
            dt  += a * ssum[d];
        }
        #pragma unroll
        for (int off = 16; off; off >>= 1) {
            nx2 += __shfl_down_sync(0xffffffffu, nx2, off);
            dt  += __shfl_down_sync(0xffffffffu, dt,  off);
        }
        if (l == 0) {
            const float loo_dot = (dt - nx2) * (1.f / 15.f);
            const float nloo2   = fmaxf((sumsq - 2.f * dt + nx2) * (1.f / 225.f), 0.f);
            const float nx      = sqrtf(nx2);
            g_invnx[j * S_SAMP + i] = 1.f / nx;
            g_sp[j * S_SAMP + i]    = loo_dot / fmaxf(nx * sqrtf(nloo2), EPS);
        }
    }
}

// ---------------------------------------------------------------------------
// k2 loaders
// ---------------------------------------------------------------------------
__device__ __forceinline__ void load_B_chunk(int g, uint32_t smB, int tid)
{
    const int nt = g >> 3, kc = g & 7;
    const uint32_t slot = smB + (uint32_t)(g & 1) * B_CHUNK_B;
    const __nv_bfloat16* src = g_Bbf + (size_t)(nt * NT) * D_DIM + kc * KC;
    #pragma unroll
    for (int it = 0; it < 8; it++) {
        const int i = tid + it * 256;     // 0..2047
        const int r = i >> 3, s = i & 7;
        cp_async16(slot + (uint32_t)(r << 7) + (uint32_t)(((s ^ (r & 7)) & 7) << 4),
                   src + (size_t)r * D_DIM + s * 8);
    }
    cp_commit();
}

// ---------------------------------------------------------------------------
// Kernel 2: bf16 mma.sync GEMM + fused logsumexp epilogue.
// 128 CTAs x 256 threads (8 warps: 4 in M x 2 in N).
// ---------------------------------------------------------------------------
__global__ void __launch_bounds__(256, 1) k2_gemm_lse(const float* __restrict__ wptr)
{
    extern __shared__ char rawsm[];
    const uint32_t smA = (smem_u32(rawsm) + 1023u) & ~1023u;  // 128 KB (8 chunks x 16KB)
    const uint32_t smB = smA + A_BYTES;                        // 2 x 32 KB

    __shared__ float s_invnx[BM], s_sp[BM], s_invnm[NT];
    __shared__ float s_red[2][BM], s_rowloss[BM];

    const int tid  = threadIdx.x;
    const int blk  = blockIdx.x;
    const int w5   = tid >> 5, lane = tid & 31;
    const int wm   = w5 & 3;        // M-warp: rows wm*32..wm*32+31
    const int wn   = w5 >> 2;       // N-warp: cols wn*128 within NT
    const int lq   = lane >> 3, l7 = lane & 7;

    if (tid < BM) {
        s_invnx[tid] = g_invnx[blk * BM + tid];
        s_sp[tid]    = g_sp[blk * BM + tid];
    }

    // A slab: all 8 K-chunks, swizzled 16KB tiles
    {
        const __nv_bfloat16* Asrc = g_Abf + (size_t)blk * BM * D_DIM;
        #pragma unroll
        for (int kc = 0; kc < 8; kc++) {
            #pragma unroll
            for (int it = 0; it < 4; it++) {
                const int i = tid + it * 256;    // 0..1023
                const int r = i >> 3, s = i & 7;
                cp_async16(smA + kc * 16384 + (uint32_t)(r << 7) +
                               (uint32_t)(((s ^ (r & 7)) & 7) << 4),
                           Asrc + (size_t)r * D_DIM + kc * KC + s * 8);
            }
        }
        cp_commit();
    }
    load_B_chunk(0, smB, tid);
    load_B_chunk(1, smB, tid);

    const float wp = log1pf(expf(wptr[0]));

    // per-thread row constants: (mt, h) -> 4 rows
    float inxr[2][2], spr[2][2];
    int   jrr[2][2];
    #pragma unroll
    for (int mt = 0; mt < 2; mt++)
        #pragma unroll
        for (int h = 0; h < 2; h++) {
            const int rl = wm * 32 + mt * 16 + h * 8 + (lane >> 2);
            inxr[mt][h] = 0.f;
            spr[mt][h]  = 0.f;
            jrr[mt][h]  = blk * 8 + (rl >> 4);
        }

    float acc[2][16][4];
    #pragma unroll
    for (int mt = 0; mt < 2; mt++)
        #pragma unroll
        for (int p = 0; p < 16; p++)
            #pragma unroll
            for (int e = 0; e < 4; e++) acc[mt][p][e] = 0.f;

    float es[2][2] = {{0.f, 0.f}, {0.f, 0.f}};

    bool consts_loaded = false;

    for (int g = 0; g < NCHUNK; g++) {
        // FIX (round-3 race): on the last iteration the newest outstanding
        // cp.async group is the chunk we consume -> must drain fully.
        if (g < NCHUNK - 1) cp_wait<1>(); else cp_wait<0>();
        __syncthreads();

        if (!consts_loaded) {   // first iteration: s_invnx/s_sp now visible
            #pragma unroll
            for (int mt = 0; mt < 2; mt++)
                #pragma unroll
                for (int h = 0; h < 2; h++) {
                    const int rl = wm * 32 + mt * 16 + h * 8 + (lane >> 2);
                    inxr[mt][h] = s_invnx[rl];
                    spr[mt][h]  = s_sp[rl];
                }
            consts_loaded = true;
        }

        if ((g & 7) == 0 && tid < NT) s_invnm[tid] = g_invnm[(g >> 3) * NT + tid];

        // ---- MMA over this chunk ----
        {
            const uint32_t Achunk = smA + (uint32_t)(g & 7) * 16384u;
            const uint32_t Bslot  = smB + (uint32_t)(g & 1) * B_CHUNK_B;
            #pragma unroll
            for (int k16 = 0; k16 < 4; k16++) {
                uint32_t a[2][4];
                #pragma unroll
                for (int mt = 0; mt < 2; mt++)
                    ldsm4(a[mt], sw_addr(Achunk, wm * 32 + mt * 16 + (lq & 1) * 8 + l7,
                                         k16 * 2 + (lq >> 1)));
                #pragma unroll
                for (int pb = 0; pb < 2; pb++) {
                    uint32_t bfr[4][4];
                    #pragma unroll
                    for (int q = 0; q < 4; q++) {
                        const int p = pb * 4 + q;   // n16 group
                        ldsm4(bfr[q], sw_addr(Bslot, wn * 128 + p * 16 + (lq >> 1) * 8 + l7,
                                              k16 * 2 + (lq & 1)));
                    }
                    #pragma unroll
                    for (int q = 0; q < 4; q++)
                        #pragma unroll
                        for (int mt = 0; mt < 2; mt++) {
                            mma16816(acc[mt][pb * 8 + q * 2],     a[mt], bfr[q][0], bfr[q][1]);
                            mma16816(acc[mt][pb * 8 + q * 2 + 1], a[mt], bfr[q][2], bfr[q][3]);
                        }
                }
            }
        }

        __syncthreads();                       // all reads of B slot g%2 done
        if (g + 2 < NCHUNK) load_B_chunk(g + 2, smB, tid);

        // ---- epilogue when an N-tile completes ----
        if ((g & 7) == 7) {
            const int nt = g >> 3;
            #pragma unroll
            for (int p = 0; p < 16; p++) {
                const int c0  = wn * 128 + p * 8 + 2 * (lane & 3);
                const float nm0 = s_invnm[c0], nm1 = s_invnm[c0 + 1];
                const int gc0 = nt * NT + c0;
                #pragma unroll
                for (int mt = 0; mt < 2; mt++)
                    #pragma unroll
                    for (int h = 0; h < 2; h++) {
                        float sim0 = acc[mt][p][h * 2 + 0] * inxr[mt][h] * nm0;
                        float sim1 = acc[mt][p][h * 2 + 1] * inxr[mt][h] * nm1;
                        if (gc0     == jrr[mt][h]) sim0 = spr[mt][h];
                        if (gc0 + 1 == jrr[mt][h]) sim1 = spr[mt][h];
                        es[mt][h] += __expf(wp * sim0) + __expf(wp * sim1);
                        acc[mt][p][h * 2 + 0] = 0.f;
                        acc[mt][p][h * 2 + 1] = 0.f;
                    }
            }
        }
    }

    // ---- reduce exp-sums: over the 4 lanes sharing a row, then over wn ----
    #pragma unroll
    for (int mt = 0; mt < 2; mt++)
        #pragma unroll
        for (int h = 0; h < 2; h++) {
            float v = es[mt][h];
            v += __shfl_xor_sync(0xffffffffu, v, 1);
            v += __shfl_xor_sync(0xffffffffu, v, 2);
            if ((lane & 3) == 0)
                s_red[wn][wm * 32 + mt * 16 + h * 8 + (lane >> 2)] = v;
        }
    __syncthreads();
    if (tid < BM) {
        const float tot = s_red[0][tid] + s_red[1][tid];
        s_rowloss[tid] = logf(tot) - wp * s_sp[tid];
    }
    __syncthreads();
    if (tid < 8) {
        float t = 0.f;
        #pragma unroll
        for (int r = 0; r < 16; r++) t += s_rowloss[tid * 16 + r];
        g_partial[blk * 8 + tid] = t;
    }
}

// ---------------------------------------------------------------------------
// Kernel 3: final reduce
// ---------------------------------------------------------------------------
__global__ void __launch_bounds__(256) k3_reduce(float* __restrict__ out)
{
    __shared__ float sred[8];
    const int tid = threadIdx.x;
    float p = 0.f;
    #pragma unroll
    for (int i = tid; i < C_CLUST; i += 256) p += g_partial[i];
    #pragma unroll
    for (int off = 16; off; off >>= 1) p += __shfl_down_sync(0xffffffffu, p, off);
    if ((tid & 31) == 0) sred[tid >> 5] = p;
    __syncthreads();
    if (tid == 0) {
        float t = 0.f;
        #pragma unroll
        for (int wi = 0; wi < 8; wi++) t += sred[wi];
        out[0] = t * (1.f / (float)NROWS);
    }
}

extern "C" void kernel_launch(void* const* d_in, const int* in_sizes, int n_in,
                              void* d_out, int out_size)
{
    const float* x = (const float*)d_in[0];
    const float* w = (const float*)d_in[1];
    // b cancels: lse(wp*sim + b) - (wp*sim_pos + b) is b-independent.
    float* out = (float*)d_out;

    cudaFuncSetAttribute(k2_gemm_lse, cudaFuncAttributeMaxDynamicSharedMemorySize, DYN_SMEM);

    k1_stats<<<C_CLUST, 256>>>(x);
    k2_gemm_lse<<<NROWS / BM, 256, DYN_SMEM>>>(w);
    k3_reduce<<<1, 256>>>(out);
}

// round 5
// speedup vs baseline: 8.1004x; 1.0594x over previous
#include <cuda_runtime.h>
#include <cuda_bf16.h>
#include <math.h>
#include <stdint.h>

#define EPS 1e-8f

#define C_CLUST 1024
#define S_SAMP  16
#define D_DIM   512
#define NROWS   (C_CLUST * S_SAMP)   // 16384

// ---- k2 tiling ----
#define BM 128                  // rows per CTA
#define NT 128                  // N-tile (centroids per tile) -> 8 tiles
#define KC 64                   // K-chunk (bf16, 128B rows)
#define NTILES 8
#define NC 64                   // total chunks = 8 tiles * 8 k-chunks
#define A_BYTES   (BM * D_DIM * 2)        // 128 KB
#define B_CHUNK_B (NT * KC * 2)           // 16 KB
#define NBUF 4                            // B ring depth
#define DYN_SMEM  (A_BYTES + NBUF * B_CHUNK_B + 1024)

// ---------------------------------------------------------------------------
// Scratch (static device globals)
// ---------------------------------------------------------------------------
__device__ __nv_bfloat16 g_Abf[NROWS * D_DIM];    // 16 MB
__device__ __nv_bfloat16 g_Bbf[C_CLUST * D_DIM];  // 1 MB (mean centroids [k][d])
__device__ float g_invnm[C_CLUST];
__device__ float g_invnx[NROWS];
__device__ float g_sp[NROWS];                     // sim_pos (exact fp32)

// ---------------------------------------------------------------------------
// helpers
// ---------------------------------------------------------------------------
__device__ __forceinline__ uint32_t smem_u32(const void* p) {
    uint32_t a;
    asm("{ .reg .u64 t; cvta.to.shared.u64 t, %1; cvt.u32.u64 %0, t; }" : "=r"(a) : "l"(p));
    return a;
}
__device__ __forceinline__ void cp_async16(uint32_t dst, const void* src) {
    asm volatile("cp.async.cg.shared.global [%0], [%1], 16;\n" :: "r"(dst), "l"(src) : "memory");
}
__device__ __forceinline__ void cp_commit() {
    asm volatile("cp.async.commit_group;\n" ::: "memory");
}
template <int N> __device__ __forceinline__ void cp_wait() {
    asm volatile("cp.async.wait_group %0;\n" :: "n"(N) : "memory");
}
__device__ __forceinline__ void ldsm4(uint32_t* r, uint32_t addr) {
    asm volatile("ldmatrix.sync.aligned.m8n8.x4.shared.b16 {%0,%1,%2,%3}, [%4];"
                 : "=r"(r[0]), "=r"(r[1]), "=r"(r[2]), "=r"(r[3]) : "r"(addr));
}
__device__ __forceinline__ void mma16816(float* c, const uint32_t* a, uint32_t b0, uint32_t b1) {
    asm volatile("mma.sync.aligned.m16n8k16.row.col.f32.bf16.bf16.f32 "
                 "{%0,%1,%2,%3}, {%4,%5,%6,%7}, {%8,%9}, {%0,%1,%2,%3};"
                 : "+f"(c[0]), "+f"(c[1]), "+f"(c[2]), "+f"(c[3])
                 : "r"(a[0]), "r"(a[1]), "r"(a[2]), "r"(a[3]), "r"(b0), "r"(b1));
}
// swizzled address inside a [rows][64 bf16] tile (128B rows)
__device__ __forceinline__ uint32_t sw_addr(uint32_t base, int row, int kseg) {
    return base + (uint32_t)(row << 7) + (uint32_t)(((kseg ^ (row & 7)) & 7) << 4);
}

// ---------------------------------------------------------------------------
// Kernel 1: per-cluster stats + bf16 conversion (A rows, B centroids).
// ---------------------------------------------------------------------------
__global__ void __launch_bounds__(256) k1_stats(const float* __restrict__ x,
                                                float* __restrict__ out)
{
    __shared__ float xs[S_SAMP * D_DIM];   // 32 KB
    __shared__ float ssum[D_DIM];
    __shared__ float sred[8];
    __shared__ float s_sumsq;

    const int j   = blockIdx.x;
    const int tid = threadIdx.x;

    if (j == 0 && tid == 0) out[0] = 0.f;   // k2 accumulates into out

    // Load + convert in one pass
    const float4* gx = (const float4*)(x + (size_t)j * S_SAMP * D_DIM);
    float4* xs4 = (float4*)xs;
    #pragma unroll
    for (int it = 0; it < 8; it++) {
        const int i4 = tid + it * 256;
        const float4 v = gx[i4];
        xs4[i4] = v;
        unsigned short h0 = __bfloat16_as_ushort(__float2bfloat16(v.x));
        unsigned short h1 = __bfloat16_as_ushort(__float2bfloat16(v.y));
        unsigned short h2 = __bfloat16_as_ushort(__float2bfloat16(v.z));
        unsigned short h3 = __bfloat16_as_ushort(__float2bfloat16(v.w));
        ((uint2*)g_Abf)[(size_t)j * 2048 + i4] =
            make_uint2(((uint32_t)h1 << 16) | h0, ((uint32_t)h3 << 16) | h2);
    }
    __syncthreads();

    // column sums over S
    const int d0 = tid, d1 = tid + 256;
    float s0 = 0.f, s1 = 0.f;
    #pragma unroll
    for (int i = 0; i < S_SAMP; i++) {
        s0 += xs[i * D_DIM + d0];
        s1 += xs[i * D_DIM + d1];
    }
    ssum[d0] = s0;
    ssum[d1] = s1;
    g_Bbf[(size_t)j * D_DIM + d0] = __float2bfloat16(s0 * (1.f / 16.f));
    g_Bbf[(size_t)j * D_DIM + d1] = __float2bfloat16(s1 * (1.f / 16.f));

    float p = s0 * s0 + s1 * s1;
    #pragma unroll
    for (int off = 16; off; off >>= 1) p += __shfl_down_sync(0xffffffffu, p, off);
    if ((tid & 31) == 0) sred[tid >> 5] = p;
    __syncthreads();
    if (tid == 0) {
        float t = 0.f;
        #pragma unroll
        for (int wi = 0; wi < 8; wi++) t += sred[wi];
        s_sumsq = t;
        g_invnm[j] = 16.f / sqrtf(t);
    }
    __syncthreads();
    const float sumsq = s_sumsq;

    const int w = tid >> 5, l = tid & 31;
    #pragma unroll
    for (int rr = 0; rr < 2; rr++) {
        const int i = w + rr * 8;
        float nx2 = 0.f, dt = 0.f;
        #pragma unroll
        for (int c = 0; c < 16; c++) {
            const int d = l + c * 32;
            const float a = xs[i * D_DIM + d];
            nx2 += a * a;
            dt  += a * ssum[d];
        }
        #pragma unroll
        for (int off = 16; off; off >>= 1) {
            nx2 += __shfl_down_sync(0xffffffffu, nx2, off);
            dt  += __shfl_down_sync(0xffffffffu, dt,  off);
        }
        if (l == 0) {
            const float loo_dot = (dt - nx2) * (1.f / 15.f);
            const float nloo2   = fmaxf((sumsq - 2.f * dt + nx2) * (1.f / 225.f), 0.f);
            const float nx      = sqrtf(nx2);
            g_invnx[j * S_SAMP + i] = 1.f / nx;
            g_sp[j * S_SAMP + i]    = loo_dot / fmaxf(nx * sqrtf(nloo2), EPS);
        }
    }
}

// ---------------------------------------------------------------------------
// Kernel 2: bf16 mma.sync GEMM + interleaved logsumexp epilogue.
// 128 CTAs x 256 threads (8 warps: wm=warp&3 over 32 rows, wn=warp>>2 over 64 cols).
// ---------------------------------------------------------------------------
__global__ void __launch_bounds__(256, 1) k2_gemm_lse(const float* __restrict__ wptr,
                                                      float* __restrict__ out)
{
    extern __shared__ char rawsm[];
    const uint32_t smA = (smem_u32(rawsm) + 1023u) & ~1023u;  // 128 KB (8 chunks x 16KB)
    const uint32_t smB = smA + A_BYTES;                        // 4 x 16 KB ring

    __shared__ float s_invnx[BM], s_sp[BM];
    __shared__ float s_invnm[2][NT];
    __shared__ float s_red[2][BM], s_rowloss[BM], s_part[8];

    const int tid  = threadIdx.x;
    const int blk  = blockIdx.x;
    const int w5   = tid >> 5, lane = tid & 31;
    const int wm   = w5 & 3;        // rows wm*32..wm*32+31
    const int wn   = w5 >> 2;       // cols wn*64 within NT
    const int lq   = lane >> 3, l7 = lane & 7;

    if (tid < BM) {
        s_invnx[tid] = g_invnx[blk * BM + tid];
        s_sp[tid]    = g_sp[blk * BM + tid];
    }

    // ---- chunk loader: B chunk gg; for gg<8 also A chunk gg (same group) ----
    const __nv_bfloat16* Asrc = g_Abf + (size_t)blk * BM * D_DIM;
    auto load_AB = [&](int gg) {
        const uint32_t slot = smB + (uint32_t)(gg & 3) * B_CHUNK_B;
        const __nv_bfloat16* bsrc =
            g_Bbf + (size_t)((gg >> 3) * NT) * D_DIM + (gg & 7) * KC;
        #pragma unroll
        for (int it = 0; it < 4; it++) {
            const int i = tid + it * 256;     // 0..1023
            const int r = i >> 3, s = i & 7;
            cp_async16(slot + (uint32_t)(r << 7) + (uint32_t)(((s ^ (r & 7)) & 7) << 4),
                       bsrc + (size_t)r * D_DIM + s * 8);
        }
        if (gg < 8) {
            #pragma unroll
            for (int it = 0; it < 4; it++) {
                const int i = tid + it * 256;
                const int r = i >> 3, s = i & 7;
                cp_async16(smA + (uint32_t)gg * 16384u + (uint32_t)(r << 7) +
                               (uint32_t)(((s ^ (r & 7)) & 7) << 4),
                           Asrc + (size_t)r * D_DIM + gg * KC + s * 8);
            }
        }
        cp_commit();
    };

    load_AB(0); load_AB(1); load_AB(2);

    const float wp = log1pf(expf(wptr[0]));
    __syncthreads();   // s_invnx/s_sp visible

    // per-thread row constants
    float inxr[2][2], spr[2][2];
    int   jrr[2][2];
    #pragma unroll
    for (int mt = 0; mt < 2; mt++)
        #pragma unroll
        for (int h = 0; h < 2; h++) {
            const int rl = wm * 32 + mt * 16 + h * 8 + (lane >> 2);
            inxr[mt][h] = s_invnx[rl];
            spr[mt][h]  = s_sp[rl];
            jrr[mt][h]  = blk * 8 + (rl >> 4);
        }

    float accA[2][8][4], accB[2][8][4];
    #pragma unroll
    for (int mt = 0; mt < 2; mt++)
        #pragma unroll
        for (int p = 0; p < 8; p++)
            #pragma unroll
            for (int e = 0; e < 4; e++) { accA[mt][p][e] = 0.f; accB[mt][p][e] = 0.f; }

    float es[2][2] = {{0.f, 0.f}, {0.f, 0.f}};

    // ---- MMA over one resident chunk ----
    auto mma_chunk = [&](int kcA, int slot, float (&acc)[2][8][4]) {
        const uint32_t Ac = smA + (uint32_t)kcA * 16384u;
        const uint32_t Bs = smB + (uint32_t)slot * B_CHUNK_B;
        #pragma unroll
        for (int k16 = 0; k16 < 4; k16++) {
            uint32_t a[2][4];
            #pragma unroll
            for (int mt = 0; mt < 2; mt++)
                ldsm4(a[mt], sw_addr(Ac, wm * 32 + mt * 16 + (lq & 1) * 8 + l7,
                                     k16 * 2 + (lq >> 1)));
            uint32_t b[4][4];
            #pragma unroll
            for (int p2 = 0; p2 < 4; p2++)
                ldsm4(b[p2], sw_addr(Bs, wn * 64 + p2 * 16 + (lq >> 1) * 8 + l7,
                                     k16 * 2 + (lq & 1)));
            #pragma unroll
            for (int p2 = 0; p2 < 4; p2++)
                #pragma unroll
                for (int mt = 0; mt < 2; mt++) {
                    mma16816(acc[mt][p2 * 2],     a[mt], b[p2][0], b[p2][1]);
                    mma16816(acc[mt][p2 * 2 + 1], a[mt], b[p2][2], b[p2][3]);
                }
        }
    };

    // ---- one epilogue slice (p-group = kcs) of tile tprev ----
    auto epi_slice = [&](int kcs, int tprev, float (&ea)[2][8][4]) {
        const int c0  = wn * 64 + kcs * 8 + (lane & 3) * 2;
        const float nm0 = s_invnm[tprev & 1][c0];
        const float nm1 = s_invnm[tprev & 1][c0 + 1];
        const int gc0 = tprev * NT + c0;
        #pragma unroll
        for (int mt = 0; mt < 2; mt++)
            #pragma unroll
            for (int h = 0; h < 2; h++) {
                float s0 = ea[mt][kcs][h * 2 + 0] * inxr[mt][h] * nm0;
                float s1 = ea[mt][kcs][h * 2 + 1] * inxr[mt][h] * nm1;
                if (gc0     == jrr[mt][h]) s0 = spr[mt][h];
                if (gc0 + 1 == jrr[mt][h]) s1 = spr[mt][h];
                es[mt][h] += __expf(wp * s0) + __expf(wp * s1);
                ea[mt][kcs][h * 2 + 0] = 0.f;
                ea[mt][kcs][h * 2 + 1] = 0.f;
            }
    };

    // ---- pipeline head: wait for chunk g, barrier, prefetch chunk g+3 ----
    auto pipe_head = [&](int g) {
        if (g < NC - 2) cp_wait<2>();
        else if (g == NC - 2) cp_wait<1>();
        else cp_wait<0>();
        __syncthreads();           // chunk g visible; all warps done with chunk g-1
        if (g + 3 < NC) load_AB(g + 3);
    };

    #pragma unroll 1
    for (int tp = 0; tp < 4; tp++) {
        // even tile t = 2*tp -> accA; epilogue of tile 2*tp-1 from accB
        #pragma unroll
        for (int kc = 0; kc < 8; kc++) {
            const int g = tp * 16 + kc;
            pipe_head(g);
            if (kc == 0 && tid < NT) s_invnm[(2 * tp) & 1][tid] = g_invnm[2 * tp * NT + tid];
            mma_chunk(kc, g & 3, accA);
            if (tp > 0) epi_slice(kc, 2 * tp - 1, accB);
        }
        // odd tile t = 2*tp+1 -> accB; epilogue of tile 2*tp from accA
        #pragma unroll
        for (int kc = 0; kc < 8; kc++) {
            const int g = tp * 16 + 8 + kc;
            pipe_head(g);
            if (kc == 0 && tid < NT) s_invnm[1][tid] = g_invnm[(2 * tp + 1) * NT + tid];
            mma_chunk(kc, g & 3, accB);
            epi_slice(kc, 2 * tp, accA);
        }
    }
    // drain: epilogue of tile 7 (accB)
    #pragma unroll
    for (int kc = 0; kc < 8; kc++) epi_slice(kc, 7, accB);

    // ---- reduce exp-sums: 4 lanes per row, then the two wn halves ----
    #pragma unroll
    for (int mt = 0; mt < 2; mt++)
        #pragma unroll
        for (int h = 0; h < 2; h++) {
            float v = es[mt][h];
            v += __shfl_xor_sync(0xffffffffu, v, 1);
            v += __shfl_xor_sync(0xffffffffu, v, 2);
            if ((lane & 3) == 0)
                s_red[wn][wm * 32 + mt * 16 + h * 8 + (lane >> 2)] = v;
        }
    __syncthreads();
    if (tid < BM) {
        const float tot = s_red[0][tid] + s_red[1][tid];
        s_rowloss[tid] = logf(tot) - wp * s_sp[tid];
    }
    __syncthreads();
    if (tid < 8) {
        float t = 0.f;
        #pragma unroll
        for (int r = 0; r < 16; r++) t += s_rowloss[tid * 16 + r];
        s_part[tid] = t;
    }
    __syncthreads();
    if (tid == 0) {
        float t = 0.f;
        #pragma unroll
        for (int i = 0; i < 8; i++) t += s_part[i];
        atomicAdd(out, t * (1.f / (float)NROWS));
    }
}

extern "C" void kernel_launch(void* const* d_in, const int* in_sizes, int n_in,
                              void* d_out, int out_size)
{
    const float* x = (const float*)d_in[0];
    const float* w = (const float*)d_in[1];
    // b cancels: lse(wp*sim + b) - (wp*sim_pos + b) is b-independent.
    float* out = (float*)d_out;

    cudaFuncSetAttribute(k2_gemm_lse, cudaFuncAttributeMaxDynamicSharedMemorySize, DYN_SMEM);

    k1_stats<<<C_CLUST, 256>>>(x, out);
    k2_gemm_lse<<<NROWS / BM, 256, DYN_SMEM>>>(w, out);
}